// round 1
// baseline (speedup 1.0000x reference)
#include <cuda_runtime.h>
#include <cstdint>
#include <math.h>

// ---------------- problem constants ----------------
static constexpr int B_   = 8;
static constexpr int T_   = 2048;
static constexpr int C_   = 1024;
static constexpr int E_   = 8;
static constexpr int H_   = 4096;
static constexpr int N_   = B_ * T_;        // 16384 tokens
static constexpr int CAP_ = 4096;           // N*K/E*CF

// ---------------- device scratch (static, allocation-free) ----------------
__device__ float         g_h[(size_t)E_ * CAP_ * H_];   // 536 MB expert hidden acts
__device__ float         g_gates[(size_t)N_ * E_];
__device__ unsigned char g_mask[N_];
__device__ int           g_dispatch[E_ * CAP_];
__device__ float         g_gslot[E_ * CAP_];
__device__ int           g_count[E_];
__device__ double        g_gatesum[E_];

// ---------------- zero out + gate sums ----------------
__global__ void zero_kernel(float* out) {
    size_t total4 = (size_t)N_ * C_ / 4;
    size_t stride = (size_t)gridDim.x * blockDim.x;
    for (size_t i = (size_t)blockIdx.x * blockDim.x + threadIdx.x; i < total4; i += stride)
        ((float4*)out)[i] = make_float4(0.f, 0.f, 0.f, 0.f);
    if (blockIdx.x == 0 && threadIdx.x < E_) g_gatesum[threadIdx.x] = 0.0;
}

// ---------------- router: logits, noisy top-2, gates, mask ----------------
__global__ void router_kernel(const float* __restrict__ x,
                              const float* __restrict__ noise,
                              const float* __restrict__ w_route,
                              const float* __restrict__ b_route,
                              const float* __restrict__ w_noise,
                              const float* __restrict__ b_noise) {
    int n    = blockIdx.x;
    int tid  = threadIdx.x;
    int lane = tid & 31;
    int wid  = tid >> 5;            // warp == expert (E_ == 8 warps)

    __shared__ float sx[C_];
    __shared__ float s_logit[E_];
    __shared__ float s_v[E_];

    // stage x row (256 threads * float4 = 1024 floats)
    ((float4*)sx)[tid] = ((const float4*)(x + (size_t)n * C_))[tid];
    __syncthreads();

    {
        int e = wid;
        const float* wr = w_route + (size_t)e * C_;
        const float* wn = w_noise + (size_t)e * C_;
        double ar = 0.0, an = 0.0;
        #pragma unroll 8
        for (int i = lane; i < C_; i += 32) {
            double xv = (double)sx[i];
            ar += xv * (double)wr[i];
            an += xv * (double)wn[i];
        }
        #pragma unroll
        for (int d = 16; d > 0; d >>= 1) {
            ar += __shfl_down_sync(0xffffffffu, ar, d);
            an += __shfl_down_sync(0xffffffffu, an, d);
        }
        if (lane == 0) {
            s_logit[e] = (float)ar + b_route[e];
            s_v[e]     = (float)an + b_noise[e];
        }
    }
    __syncthreads();

    if (tid == 0) {
        float noisy[E_];
        #pragma unroll
        for (int e = 0; e < E_; e++) {
            float v  = s_v[e];
            float sp = fmaxf(v, 0.f) + log1pf(expf(-fabsf(v)));   // softplus
            noisy[e] = s_logit[e] + noise[(size_t)n * E_ + e] * sp;
        }
        // top-2 (lowest index wins ties, matching lax.top_k)
        int i1 = 0;
        #pragma unroll
        for (int e = 1; e < E_; e++) if (noisy[e] > noisy[i1]) i1 = e;
        int i2 = (i1 == 0) ? 1 : 0;
        #pragma unroll
        for (int e = 0; e < E_; e++) if (e != i1 && noisy[e] > noisy[i2]) i2 = e;

        // softmax over the 2 selected (others exp(-1e30-m) == 0 in fp32)
        float e2 = expf(noisy[i2] - noisy[i1]);
        float denom = 1.f + e2;
        float g1 = 1.f / denom;
        float g2 = e2  / denom;

        #pragma unroll
        for (int e = 0; e < E_; e++)
            g_gates[(size_t)n * E_ + e] = (e == i1) ? g1 : ((e == i2) ? g2 : 0.f);
        g_mask[n] = (unsigned char)((1u << i1) | (1u << i2));
        atomicAdd(&g_gatesum[i1], (double)g1);
        atomicAdd(&g_gatesum[i2], (double)g2);
    }
}

// ---------------- per-expert capacity scan + dispatch ----------------
__global__ void scan_kernel() {
    int e    = blockIdx.x;
    int tid  = threadIdx.x;          // 1024 threads
    int lane = tid & 31;
    int wid  = tid >> 5;

    __shared__ int wsum[32];
    __shared__ int s_total;

    int offset = 0;
    for (int chunk = 0; chunk < N_ / 1024; chunk++) {
        int n   = chunk * 1024 + tid;
        int bit = (g_mask[n] >> e) & 1;

        unsigned bal = __ballot_sync(0xffffffffu, bit);
        int pre  = __popc(bal & ((1u << lane) - 1u));
        int wtot = __popc(bal);
        if (lane == 0) wsum[wid] = wtot;
        __syncthreads();
        if (tid < 32) {
            int v0 = wsum[tid];
            int v  = v0;
            #pragma unroll
            for (int d = 1; d < 32; d <<= 1) {
                int t = __shfl_up_sync(0xffffffffu, v, d);
                if (tid >= d) v += t;
            }
            if (tid == 31) s_total = v;
            wsum[tid] = v - v0;      // exclusive
        }
        __syncthreads();
        if (bit) {
            int pos = offset + wsum[wid] + pre;
            if (pos < CAP_) {
                g_dispatch[e * CAP_ + pos] = n;
                g_gslot[e * CAP_ + pos]    = g_gates[(size_t)n * E_ + e];
            }
        }
        offset += s_total;
        __syncthreads();
    }
    if (tid == 0) g_count[e] = offset < CAP_ ? offset : CAP_;
}

// ---------------- load-balance loss ----------------
__global__ void loss_kernel(float* out) {
    if (threadIdx.x == 0 && blockIdx.x == 0) {
        double acc = 0.0;
        #pragma unroll
        for (int e = 0; e < E_; e++) {
            double fr = g_gatesum[e] / (double)N_;
            double d  = fr - 1.0 / (double)E_;
            acc += d * d;
        }
        out[(size_t)N_ * C_] = (float)(0.01 * (acc / (double)E_));
    }
}

// ---------------- SGEMM tiles ----------------
static constexpr int BM = 128, BN = 128, BK = 8, TM = 8, TN = 8;

// GEMM1: h[e] = relu( x[dispatch[e]] @ w1[e] + b1[e] )   (M<=CAP, K=C, N=H)
__global__ __launch_bounds__(256, 2)
void ffn1_kernel(const float* __restrict__ x,
                 const float* __restrict__ w1,
                 const float* __restrict__ b1) {
    int e   = blockIdx.z;
    int cnt = g_count[e];
    int bm  = blockIdx.y, bn = blockIdx.x;
    if (bm * BM >= cnt) return;

    __shared__ float As[BK][BM];
    __shared__ float Bs[BK][BN];
    __shared__ int   stok[BM];

    int tid = threadIdx.x;
    if (tid < BM) {
        int r = bm * BM + tid;
        stok[tid] = (r < cnt) ? g_dispatch[e * CAP_ + r] : -1;
    }
    __syncthreads();

    int arow = tid >> 1, ak = (tid & 1) * 4;
    int brow = tid >> 5, bcol = (tid & 31) * 4;
    int ty = tid >> 4, tx = tid & 15;

    int tok = stok[arow];
    const float* Arow  = x  + (size_t)(tok < 0 ? 0 : tok) * C_;
    const float* Bbase = w1 + (size_t)e * C_ * H_ + (size_t)bn * BN;

    float acc[TM][TN];
    #pragma unroll
    for (int i = 0; i < TM; i++)
        #pragma unroll
        for (int j = 0; j < TN; j++) acc[i][j] = 0.f;

    for (int kk = 0; kk < C_; kk += BK) {
        float4 av = make_float4(0.f, 0.f, 0.f, 0.f);
        if (tok >= 0) av = *(const float4*)(Arow + kk + ak);
        As[ak + 0][arow] = av.x;
        As[ak + 1][arow] = av.y;
        As[ak + 2][arow] = av.z;
        As[ak + 3][arow] = av.w;
        *(float4*)&Bs[brow][bcol] = *(const float4*)(Bbase + (size_t)(kk + brow) * H_ + bcol);
        __syncthreads();
        #pragma unroll
        for (int k = 0; k < BK; k++) {
            float ra[TM], rb[TN];
            *(float4*)&ra[0] = *(const float4*)&As[k][ty * TM];
            *(float4*)&ra[4] = *(const float4*)&As[k][ty * TM + 4];
            *(float4*)&rb[0] = *(const float4*)&Bs[k][tx * TN];
            *(float4*)&rb[4] = *(const float4*)&Bs[k][tx * TN + 4];
            #pragma unroll
            for (int i = 0; i < TM; i++)
                #pragma unroll
                for (int j = 0; j < TN; j++)
                    acc[i][j] = fmaf(ra[i], rb[j], acc[i][j]);
        }
        __syncthreads();
    }

    int row0 = bm * BM + ty * TM;
    int col0 = bn * BN + tx * TN;
    #pragma unroll
    for (int i = 0; i < TM; i++) {
        int row = row0 + i;
        if (row < cnt) {
            float* hp = g_h + ((size_t)e * CAP_ + row) * H_ + col0;
            #pragma unroll
            for (int j = 0; j < TN; j++) {
                float v = acc[i][j] + b1[(size_t)e * H_ + col0 + j];
                hp[j] = v > 0.f ? v : 0.f;
            }
        }
    }
}

// GEMM2: out[tok] += gate * ( h[e] @ w2[e] + b2[e] )   (M<=CAP, K=H, N=C)
__global__ __launch_bounds__(256, 2)
void ffn2_kernel(const float* __restrict__ w2,
                 const float* __restrict__ b2,
                 float* __restrict__ out) {
    int e   = blockIdx.z;
    int cnt = g_count[e];
    int bm  = blockIdx.y, bn = blockIdx.x;
    if (bm * BM >= cnt) return;

    __shared__ float As[BK][BM];
    __shared__ float Bs[BK][BN];

    int tid  = threadIdx.x;
    int arow = tid >> 1, ak = (tid & 1) * 4;
    int brow = tid >> 5, bcol = (tid & 31) * 4;
    int ty = tid >> 4, tx = tid & 15;

    int grow = bm * BM + arow;
    bool avalid = grow < cnt;
    const float* Arow  = g_h + ((size_t)e * CAP_ + (avalid ? grow : 0)) * H_;
    const float* Bbase = w2  + (size_t)e * H_ * C_ + (size_t)bn * BN;

    float acc[TM][TN];
    #pragma unroll
    for (int i = 0; i < TM; i++)
        #pragma unroll
        for (int j = 0; j < TN; j++) acc[i][j] = 0.f;

    for (int kk = 0; kk < H_; kk += BK) {
        float4 av = avalid ? *(const float4*)(Arow + kk + ak)
                           : make_float4(0.f, 0.f, 0.f, 0.f);
        As[ak + 0][arow] = av.x;
        As[ak + 1][arow] = av.y;
        As[ak + 2][arow] = av.z;
        As[ak + 3][arow] = av.w;
        *(float4*)&Bs[brow][bcol] = *(const float4*)(Bbase + (size_t)(kk + brow) * C_ + bcol);
        __syncthreads();
        #pragma unroll
        for (int k = 0; k < BK; k++) {
            float ra[TM], rb[TN];
            *(float4*)&ra[0] = *(const float4*)&As[k][ty * TM];
            *(float4*)&ra[4] = *(const float4*)&As[k][ty * TM + 4];
            *(float4*)&rb[0] = *(const float4*)&Bs[k][tx * TN];
            *(float4*)&rb[4] = *(const float4*)&Bs[k][tx * TN + 4];
            #pragma unroll
            for (int i = 0; i < TM; i++)
                #pragma unroll
                for (int j = 0; j < TN; j++)
                    acc[i][j] = fmaf(ra[i], rb[j], acc[i][j]);
        }
        __syncthreads();
    }

    int row0 = bm * BM + ty * TM;
    int col0 = bn * BN + tx * TN;
    #pragma unroll
    for (int i = 0; i < TM; i++) {
        int row = row0 + i;
        if (row < cnt) {
            int   tok = g_dispatch[e * CAP_ + row];
            float g   = g_gslot[e * CAP_ + row];
            float* op = out + (size_t)tok * C_ + col0;
            #pragma unroll
            for (int j = 0; j < TN; j++) {
                float v = (acc[i][j] + b2[(size_t)e * C_ + col0 + j]) * g;
                atomicAdd(&op[j], v);
            }
        }
    }
}

// ---------------- launch ----------------
extern "C" void kernel_launch(void* const* d_in, const int* in_sizes, int n_in,
                              void* d_out, int out_size) {
    const float* x       = (const float*)d_in[0];
    const float* noise   = (const float*)d_in[1];
    const float* w_route = (const float*)d_in[2];
    const float* b_route = (const float*)d_in[3];
    const float* w_noise = (const float*)d_in[4];
    const float* b_noise = (const float*)d_in[5];
    const float* w1      = (const float*)d_in[6];
    const float* b1      = (const float*)d_in[7];
    const float* w2      = (const float*)d_in[8];
    const float* b2      = (const float*)d_in[9];
    float* out = (float*)d_out;

    zero_kernel<<<2048, 256>>>(out);
    router_kernel<<<N_, 256>>>(x, noise, w_route, b_route, w_noise, b_noise);
    scan_kernel<<<E_, 1024>>>();
    loss_kernel<<<1, 32>>>(out);
    ffn1_kernel<<<dim3(H_ / BN, CAP_ / BM, E_), 256>>>(x, w1, b1);
    ffn2_kernel<<<dim3(C_ / BN, CAP_ / BM, E_), 256>>>(w2, b2, out);
}

// round 2
// speedup vs baseline: 1.0003x; 1.0003x over previous
#include <cuda_runtime.h>
#include <cstdint>
#include <math.h>

// ---------------- problem constants ----------------
static constexpr int B_   = 8;
static constexpr int T_   = 2048;
static constexpr int C_   = 1024;
static constexpr int E_   = 8;
static constexpr int H_   = 4096;
static constexpr int N_   = B_ * T_;        // 16384 tokens
static constexpr int CAP_ = 4096;           // N*K/E*CF

// ---------------- device scratch (static, allocation-free) ----------------
__device__ float         g_h[(size_t)E_ * CAP_ * H_];   // 536 MB expert hidden acts
__device__ float         g_gates[(size_t)N_ * E_];
__device__ unsigned char g_mask[N_];
__device__ int           g_dispatch[E_ * CAP_];
__device__ float         g_gslot[E_ * CAP_];
__device__ int           g_count[E_];
__device__ double        g_gatesum[E_];

// ---------------- zero out + gate sums ----------------
__global__ void zero_kernel(float* out) {
    size_t total4 = (size_t)N_ * C_ / 4;
    size_t stride = (size_t)gridDim.x * blockDim.x;
    for (size_t i = (size_t)blockIdx.x * blockDim.x + threadIdx.x; i < total4; i += stride)
        ((float4*)out)[i] = make_float4(0.f, 0.f, 0.f, 0.f);
    if (blockIdx.x == 0 && threadIdx.x < E_) g_gatesum[threadIdx.x] = 0.0;
}

// ---------------- router: logits, noisy top-2, gates, mask ----------------
__global__ void router_kernel(const float* __restrict__ x,
                              const float* __restrict__ noise,
                              const float* __restrict__ w_route,
                              const float* __restrict__ b_route,
                              const float* __restrict__ w_noise,
                              const float* __restrict__ b_noise) {
    int n    = blockIdx.x;
    int tid  = threadIdx.x;
    int lane = tid & 31;
    int wid  = tid >> 5;            // warp == expert (E_ == 8 warps)

    __shared__ float sx[C_];
    __shared__ float s_logit[E_];
    __shared__ float s_v[E_];

    // stage x row (256 threads * float4 = 1024 floats)
    ((float4*)sx)[tid] = ((const float4*)(x + (size_t)n * C_))[tid];
    __syncthreads();

    {
        int e = wid;
        const float* wr = w_route + (size_t)e * C_;
        const float* wn = w_noise + (size_t)e * C_;
        double ar = 0.0, an = 0.0;
        #pragma unroll 8
        for (int i = lane; i < C_; i += 32) {
            double xv = (double)sx[i];
            ar += xv * (double)wr[i];
            an += xv * (double)wn[i];
        }
        #pragma unroll
        for (int d = 16; d > 0; d >>= 1) {
            ar += __shfl_down_sync(0xffffffffu, ar, d);
            an += __shfl_down_sync(0xffffffffu, an, d);
        }
        if (lane == 0) {
            s_logit[e] = (float)ar + b_route[e];
            s_v[e]     = (float)an + b_noise[e];
        }
    }
    __syncthreads();

    if (tid == 0) {
        float noisy[E_];
        #pragma unroll
        for (int e = 0; e < E_; e++) {
            float v  = s_v[e];
            float sp = fmaxf(v, 0.f) + log1pf(expf(-fabsf(v)));   // softplus
            noisy[e] = s_logit[e] + noise[(size_t)n * E_ + e] * sp;
        }
        // top-2 (lowest index wins ties, matching lax.top_k)
        int i1 = 0;
        #pragma unroll
        for (int e = 1; e < E_; e++) if (noisy[e] > noisy[i1]) i1 = e;
        int i2 = (i1 == 0) ? 1 : 0;
        #pragma unroll
        for (int e = 0; e < E_; e++) if (e != i1 && noisy[e] > noisy[i2]) i2 = e;

        // softmax over the 2 selected (others exp(-1e30-m) == 0 in fp32)
        float e2 = expf(noisy[i2] - noisy[i1]);
        float denom = 1.f + e2;
        float g1 = 1.f / denom;
        float g2 = e2  / denom;

        #pragma unroll
        for (int e = 0; e < E_; e++)
            g_gates[(size_t)n * E_ + e] = (e == i1) ? g1 : ((e == i2) ? g2 : 0.f);
        g_mask[n] = (unsigned char)((1u << i1) | (1u << i2));
        atomicAdd(&g_gatesum[i1], (double)g1);
        atomicAdd(&g_gatesum[i2], (double)g2);
    }
}

// ---------------- per-expert capacity scan + dispatch ----------------
__global__ void scan_kernel() {
    int e    = blockIdx.x;
    int tid  = threadIdx.x;          // 1024 threads
    int lane = tid & 31;
    int wid  = tid >> 5;

    __shared__ int wsum[32];
    __shared__ int s_total;

    int offset = 0;
    for (int chunk = 0; chunk < N_ / 1024; chunk++) {
        int n   = chunk * 1024 + tid;
        int bit = (g_mask[n] >> e) & 1;

        unsigned bal = __ballot_sync(0xffffffffu, bit);
        int pre  = __popc(bal & ((1u << lane) - 1u));
        int wtot = __popc(bal);
        if (lane == 0) wsum[wid] = wtot;
        __syncthreads();
        if (tid < 32) {
            int v0 = wsum[tid];
            int v  = v0;
            #pragma unroll
            for (int d = 1; d < 32; d <<= 1) {
                int t = __shfl_up_sync(0xffffffffu, v, d);
                if (tid >= d) v += t;
            }
            if (tid == 31) s_total = v;
            wsum[tid] = v - v0;      // exclusive
        }
        __syncthreads();
        if (bit) {
            int pos = offset + wsum[wid] + pre;
            if (pos < CAP_) {
                g_dispatch[e * CAP_ + pos] = n;
                g_gslot[e * CAP_ + pos]    = g_gates[(size_t)n * E_ + e];
            }
        }
        offset += s_total;
        __syncthreads();
    }
    if (tid == 0) g_count[e] = offset < CAP_ ? offset : CAP_;
}

// ---------------- load-balance loss ----------------
__global__ void loss_kernel(float* out) {
    if (threadIdx.x == 0 && blockIdx.x == 0) {
        double acc = 0.0;
        #pragma unroll
        for (int e = 0; e < E_; e++) {
            double fr = g_gatesum[e] / (double)N_;
            double d  = fr - 1.0 / (double)E_;
            acc += d * d;
        }
        out[(size_t)N_ * C_] = (float)(0.01 * (acc / (double)E_));
    }
}

// ---------------- SGEMM tiles ----------------
static constexpr int BM = 128, BN = 128, BK = 8, TM = 8, TN = 8;

// GEMM1: h[e] = relu( x[dispatch[e]] @ w1[e] + b1[e] )   (M<=CAP, K=C, N=H)
__global__ __launch_bounds__(256, 2)
void ffn1_kernel(const float* __restrict__ x,
                 const float* __restrict__ w1,
                 const float* __restrict__ b1) {
    int e   = blockIdx.z;
    int cnt = g_count[e];
    int bm  = blockIdx.y, bn = blockIdx.x;
    if (bm * BM >= cnt) return;

    __shared__ float As[BK][BM];
    __shared__ float Bs[BK][BN];
    __shared__ int   stok[BM];

    int tid = threadIdx.x;
    if (tid < BM) {
        int r = bm * BM + tid;
        stok[tid] = (r < cnt) ? g_dispatch[e * CAP_ + r] : -1;
    }
    __syncthreads();

    int arow = tid >> 1, ak = (tid & 1) * 4;
    int brow = tid >> 5, bcol = (tid & 31) * 4;
    int ty = tid >> 4, tx = tid & 15;

    int tok = stok[arow];
    const float* Arow  = x  + (size_t)(tok < 0 ? 0 : tok) * C_;
    const float* Bbase = w1 + (size_t)e * C_ * H_ + (size_t)bn * BN;

    float acc[TM][TN];
    #pragma unroll
    for (int i = 0; i < TM; i++)
        #pragma unroll
        for (int j = 0; j < TN; j++) acc[i][j] = 0.f;

    for (int kk = 0; kk < C_; kk += BK) {
        float4 av = make_float4(0.f, 0.f, 0.f, 0.f);
        if (tok >= 0) av = *(const float4*)(Arow + kk + ak);
        As[ak + 0][arow] = av.x;
        As[ak + 1][arow] = av.y;
        As[ak + 2][arow] = av.z;
        As[ak + 3][arow] = av.w;
        *(float4*)&Bs[brow][bcol] = *(const float4*)(Bbase + (size_t)(kk + brow) * H_ + bcol);
        __syncthreads();
        #pragma unroll
        for (int k = 0; k < BK; k++) {
            float ra[TM], rb[TN];
            *(float4*)&ra[0] = *(const float4*)&As[k][ty * TM];
            *(float4*)&ra[4] = *(const float4*)&As[k][ty * TM + 4];
            *(float4*)&rb[0] = *(const float4*)&Bs[k][tx * TN];
            *(float4*)&rb[4] = *(const float4*)&Bs[k][tx * TN + 4];
            #pragma unroll
            for (int i = 0; i < TM; i++)
                #pragma unroll
                for (int j = 0; j < TN; j++)
                    acc[i][j] = fmaf(ra[i], rb[j], acc[i][j]);
        }
        __syncthreads();
    }

    int row0 = bm * BM + ty * TM;
    int col0 = bn * BN + tx * TN;
    #pragma unroll
    for (int i = 0; i < TM; i++) {
        int row = row0 + i;
        if (row < cnt) {
            float* hp = g_h + ((size_t)e * CAP_ + row) * H_ + col0;
            #pragma unroll
            for (int j = 0; j < TN; j++) {
                float v = acc[i][j] + b1[(size_t)e * H_ + col0 + j];
                hp[j] = v > 0.f ? v : 0.f;
            }
        }
    }
}

// GEMM2: out[tok] += gate * ( h[e] @ w2[e] + b2[e] )   (M<=CAP, K=H, N=C)
__global__ __launch_bounds__(256, 2)
void ffn2_kernel(const float* __restrict__ w2,
                 const float* __restrict__ b2,
                 float* __restrict__ out) {
    int e   = blockIdx.z;
    int cnt = g_count[e];
    int bm  = blockIdx.y, bn = blockIdx.x;
    if (bm * BM >= cnt) return;

    __shared__ float As[BK][BM];
    __shared__ float Bs[BK][BN];

    int tid  = threadIdx.x;
    int arow = tid >> 1, ak = (tid & 1) * 4;
    int brow = tid >> 5, bcol = (tid & 31) * 4;
    int ty = tid >> 4, tx = tid & 15;

    int grow = bm * BM + arow;
    bool avalid = grow < cnt;
    const float* Arow  = g_h + ((size_t)e * CAP_ + (avalid ? grow : 0)) * H_;
    const float* Bbase = w2  + (size_t)e * H_ * C_ + (size_t)bn * BN;

    float acc[TM][TN];
    #pragma unroll
    for (int i = 0; i < TM; i++)
        #pragma unroll
        for (int j = 0; j < TN; j++) acc[i][j] = 0.f;

    for (int kk = 0; kk < H_; kk += BK) {
        float4 av = avalid ? *(const float4*)(Arow + kk + ak)
                           : make_float4(0.f, 0.f, 0.f, 0.f);
        As[ak + 0][arow] = av.x;
        As[ak + 1][arow] = av.y;
        As[ak + 2][arow] = av.z;
        As[ak + 3][arow] = av.w;
        *(float4*)&Bs[brow][bcol] = *(const float4*)(Bbase + (size_t)(kk + brow) * C_ + bcol);
        __syncthreads();
        #pragma unroll
        for (int k = 0; k < BK; k++) {
            float ra[TM], rb[TN];
            *(float4*)&ra[0] = *(const float4*)&As[k][ty * TM];
            *(float4*)&ra[4] = *(const float4*)&As[k][ty * TM + 4];
            *(float4*)&rb[0] = *(const float4*)&Bs[k][tx * TN];
            *(float4*)&rb[4] = *(const float4*)&Bs[k][tx * TN + 4];
            #pragma unroll
            for (int i = 0; i < TM; i++)
                #pragma unroll
                for (int j = 0; j < TN; j++)
                    acc[i][j] = fmaf(ra[i], rb[j], acc[i][j]);
        }
        __syncthreads();
    }

    int row0 = bm * BM + ty * TM;
    int col0 = bn * BN + tx * TN;
    #pragma unroll
    for (int i = 0; i < TM; i++) {
        int row = row0 + i;
        if (row < cnt) {
            int   tok = g_dispatch[e * CAP_ + row];
            float g   = g_gslot[e * CAP_ + row];
            float* op = out + (size_t)tok * C_ + col0;
            #pragma unroll
            for (int j = 0; j < TN; j++) {
                float v = (acc[i][j] + b2[(size_t)e * C_ + col0 + j]) * g;
                atomicAdd(&op[j], v);
            }
        }
    }
}

// ---------------- launch ----------------
extern "C" void kernel_launch(void* const* d_in, const int* in_sizes, int n_in,
                              void* d_out, int out_size) {
    const float* x       = (const float*)d_in[0];
    const float* noise   = (const float*)d_in[1];
    const float* w_route = (const float*)d_in[2];
    const float* b_route = (const float*)d_in[3];
    const float* w_noise = (const float*)d_in[4];
    const float* b_noise = (const float*)d_in[5];
    const float* w1      = (const float*)d_in[6];
    const float* b1      = (const float*)d_in[7];
    const float* w2      = (const float*)d_in[8];
    const float* b2      = (const float*)d_in[9];
    float* out = (float*)d_out;

    zero_kernel<<<2048, 256>>>(out);
    router_kernel<<<N_, 256>>>(x, noise, w_route, b_route, w_noise, b_noise);
    scan_kernel<<<E_, 1024>>>();
    loss_kernel<<<1, 32>>>(out);
    ffn1_kernel<<<dim3(H_ / BN, CAP_ / BM, E_), 256>>>(x, w1, b1);
    ffn2_kernel<<<dim3(C_ / BN, CAP_ / BM, E_), 256>>>(w2, b2, out);
}